// round 1
// baseline (speedup 1.0000x reference)
#include <cuda_runtime.h>
#include <math_constants.h>

// Problem constants (from reference setup_inputs)
#define N_IMG 2
#define C_CH  256
#define H_F   64
#define W_F   64
#define R_ROI 128
#define PH    7
#define PW    7
#define SCALE 0.0625f

// total outputs = R * C * PH * PW = 128*256*49 = 1,605,632

__global__ void roipool_kernel(const float* __restrict__ feat,
                               const float* __restrict__ rois,
                               float* __restrict__ out,
                               int total)
{
    int idx = blockIdx.x * blockDim.x + threadIdx.x;
    if (idx >= total) return;

    int pw = idx % PW;
    int ph = (idx / PW) % PH;
    int c  = (idx / (PW * PH)) % C_CH;
    int r  = idx / (PW * PH * C_CH);

    const float* roi = rois + r * 5;
    int b  = (int)roi[0];
    // jnp.round = round-half-to-even -> rintf (default RN mode)
    int sw = (int)rintf(roi[1] * SCALE);
    int sh = (int)rintf(roi[2] * SCALE);
    int ew = (int)rintf(roi[3] * SCALE);
    int eh = (int)rintf(roi[4] * SCALE);

    float roi_w = (float)max(ew - sw + 1, 1);
    float roi_h = (float)max(eh - sh + 1, 1);
    float bin_h = roi_h * (1.0f / PH);
    float bin_w = roi_w * (1.0f / PW);

    int hstart = min(max((int)floorf((float)ph * bin_h) + sh, 0), H_F);
    int hend   = min(max((int)ceilf(((float)ph + 1.0f) * bin_h) + sh, 0), H_F);
    int wstart = min(max((int)floorf((float)pw * bin_w) + sw, 0), W_F);
    int wend   = min(max((int)ceilf(((float)pw + 1.0f) * bin_w) + sw, 0), W_F);

    bool empty = (hend <= hstart) || (wend <= wstart);

    float m = empty ? 0.0f : -CUDART_INF_F;
    const float* fp = feat + ((size_t)(b * C_CH + c)) * (H_F * W_F);

    for (int h = hstart; h < hend; ++h) {
        const float* row = fp + h * W_F;
        for (int w = wstart; w < wend; ++w) {
            m = fmaxf(m, __ldg(row + w));
        }
    }
    out[idx] = m;
}

extern "C" void kernel_launch(void* const* d_in, const int* in_sizes, int n_in,
                              void* d_out, int out_size)
{
    const float* feat = (const float*)d_in[0];
    const float* rois = (const float*)d_in[1];
    float* out = (float*)d_out;

    int total = R_ROI * C_CH * PH * PW;
    int threads = 256;
    int blocks = (total + threads - 1) / threads;
    roipool_kernel<<<blocks, threads>>>(feat, rois, out, total);
}